// round 1
// baseline (speedup 1.0000x reference)
#include <cuda_runtime.h>
#include <cuda_bf16.h>
#include <math.h>

#define DIMC   96
#define DINNER 192
#define DSTATE 16
#define DCONV  4
#define DTRANK 6
#define NSWAP  59
#define BSZ    2
#define SEQ    6400
#define TOK    (BSZ*SEQ)     // 12800
#define CHUNK  64
#define NCH    (SEQ/CHUNK)   // 100
#define XPROJ_OUT 224        // 192 dt + 16 B + 16 C

// ---------------- scratch (static device globals; no allocation) ------------
__device__ __align__(16) float g_xs1[TOK*DIMC];
__device__ __align__(16) float g_xs2[TOK*DIMC];
__device__ __align__(16) float g_xz [TOK*2*DINNER];
__device__ __align__(16) float g_xc [TOK*DINNER];
__device__ __align__(16) float g_dbc[TOK*XPROJ_OUT];
__device__ __align__(16) float g_w2 [XPROJ_OUT*DINNER];
__device__ __align__(16) float g_carryP[BSZ*NCH*DINNER*DSTATE];
__device__ __align__(16) float g_carryF[BSZ*NCH*DINNER*DSTATE];
__device__ __align__(16) float g_hinit [BSZ*NCH*DINNER*DSTATE];
__device__ __align__(16) float g_yg [TOK*DINNER];

// ---------------- K0: fold dt_w @ xproj_w[:6] and pack B/C rows -------------
__global__ void prep_w2_kernel(const float* __restrict__ xproj,   // [38,192]
                               const float* __restrict__ dtw,     // [192,6]
                               float* __restrict__ w2)            // [224,192]
{
    int idx = blockIdx.x * blockDim.x + threadIdx.x;
    if (idx >= XPROJ_OUT*DINNER) return;
    int r = idx / DINNER, c = idx % DINNER;
    float v;
    if (r < DINNER) {
        v = 0.f;
        #pragma unroll
        for (int j = 0; j < DTRANK; j++)
            v += dtw[r*DTRANK + j] * xproj[j*DINNER + c];
    } else if (r < DINNER + DSTATE) {
        v = xproj[(DTRANK + (r - DINNER))*DINNER + c];
    } else {
        v = xproj[(DTRANK + DSTATE + (r - DINNER - DSTATE))*DINNER + c];
    }
    w2[idx] = v;
}

// ---------------- K1: layernorm + token-swap + channel shuffle --------------
__global__ void ln_swap_shuffle_kernel(const float* __restrict__ x1,
                                       const float* __restrict__ x2,
                                       const float* __restrict__ g1, const float* __restrict__ b1,
                                       const float* __restrict__ g2, const float* __restrict__ b2,
                                       float* __restrict__ xs1, float* __restrict__ xs2)
{
    __shared__ float s1[8][DIMC];
    __shared__ float s2[8][DIMC];
    int w = threadIdx.x >> 5, lane = threadIdx.x & 31;
    int token = blockIdx.x * 8 + w;       // TOK divisible by 8
    const float* p1 = x1 + (size_t)token*DIMC;
    const float* p2 = x2 + (size_t)token*DIMC;
    float a0 = p1[lane], a1 = p1[lane+32], a2 = p1[lane+64];
    float c0 = p2[lane], c1 = p2[lane+32], c2 = p2[lane+64];
    float sum1 = a0+a1+a2, sq1 = a0*a0+a1*a1+a2*a2;
    float sum2 = c0+c1+c2, sq2 = c0*c0+c1*c1+c2*c2;
    #pragma unroll
    for (int o = 16; o > 0; o >>= 1) {
        sum1 += __shfl_xor_sync(0xffffffffu, sum1, o);
        sq1  += __shfl_xor_sync(0xffffffffu, sq1,  o);
        sum2 += __shfl_xor_sync(0xffffffffu, sum2, o);
        sq2  += __shfl_xor_sync(0xffffffffu, sq2,  o);
    }
    float m1 = sum1 * (1.f/DIMC), v1 = sq1 * (1.f/DIMC) - m1*m1;
    float m2 = sum2 * (1.f/DIMC), v2 = sq2 * (1.f/DIMC) - m2*m2;
    float r1 = rsqrtf(v1 + 1e-5f), r2 = rsqrtf(v2 + 1e-5f);
    #pragma unroll
    for (int k = 0; k < 3; k++) {
        int ch = lane + 32*k;
        float xv = (k==0? a0 : k==1? a1 : a2);
        float yv = (k==0? c0 : k==1? c1 : c2);
        s1[w][ch] = (xv - m1) * r1 * g1[ch] + b1[ch];
        s2[w][ch] = (yv - m2) * r2 * g2[ch] + b2[ch];
    }
    __syncwarp();
    #pragma unroll
    for (int k = 0; k < 3; k++) {
        int ch  = lane + 32*k;
        int src = (ch & 1)*48 + (ch >> 1);        // channel shuffle (groups=2)
        float p2v = s2[w][src];                   // x2s == shuffled x2n
        float p1v = (src < NSWAP) ? s2[w][src] : s1[w][src];
        xs1[(size_t)token*DIMC + ch] = p1v;
        xs2[(size_t)token*DIMC + ch] = p2v;
    }
}

// ---------------- K2: register-tiled fp32 GEMM: out = A[M,K] @ W[N,K]^T -----
// MODE 0: plain   MODE 1: softplus(v+bias[col]) for col<192   MODE 2: +resid
template<int MODE>
__global__ void gemm_kernel(const float* __restrict__ A, const float* __restrict__ W,
                            float* __restrict__ out, int M, int N, int K,
                            const float* __restrict__ bias,
                            const float* __restrict__ resid)
{
    __shared__ float sA[64][33];
    __shared__ float sB[64][33];
    int tid = threadIdx.x;
    int tx = tid & 15, ty = tid >> 4;
    int m0 = blockIdx.x * 64;
    int n0 = blockIdx.y * 64;
    float acc[4][4] = {};
    for (int k0 = 0; k0 < K; k0 += 32) {
        #pragma unroll
        for (int v = 0; v < 2; v++) {
            int i  = tid*2 + v;
            int r  = i >> 3;
            int c4 = (i & 7) << 2;
            float4 av = *reinterpret_cast<const float4*>(A + (size_t)(m0+r)*K + k0 + c4);
            sA[r][c4+0]=av.x; sA[r][c4+1]=av.y; sA[r][c4+2]=av.z; sA[r][c4+3]=av.w;
            int n = n0 + r;
            float4 wv = make_float4(0.f,0.f,0.f,0.f);
            if (n < N) wv = *reinterpret_cast<const float4*>(W + (size_t)n*K + k0 + c4);
            sB[r][c4+0]=wv.x; sB[r][c4+1]=wv.y; sB[r][c4+2]=wv.z; sB[r][c4+3]=wv.w;
        }
        __syncthreads();
        #pragma unroll
        for (int kk = 0; kk < 32; kk++) {
            float a[4], b[4];
            #pragma unroll
            for (int i = 0; i < 4; i++) a[i] = sA[ty*4+i][kk];
            #pragma unroll
            for (int j = 0; j < 4; j++) b[j] = sB[tx*4+j][kk];
            #pragma unroll
            for (int i = 0; i < 4; i++)
                #pragma unroll
                for (int j = 0; j < 4; j++)
                    acc[i][j] += a[i]*b[j];
        }
        __syncthreads();
    }
    #pragma unroll
    for (int i = 0; i < 4; i++) {
        int row = m0 + ty*4 + i;
        #pragma unroll
        for (int j = 0; j < 4; j++) {
            int col = n0 + tx*4 + j;
            if (col < N) {
                float v = acc[i][j];
                if (MODE == 1) {
                    if (col < DINNER) {
                        v += bias[col];
                        v = (v > 20.f) ? v : log1pf(__expf(v));
                    }
                } else if (MODE == 2) {
                    v += resid[(size_t)row*N + col];
                }
                out[(size_t)row*N + col] = v;
            }
        }
    }
}

// ---------------- K3: depthwise causal conv(4) + silu -----------------------
__global__ void conv_silu_kernel(const float* __restrict__ xz,
                                 const float* __restrict__ cw,
                                 const float* __restrict__ cb,
                                 float* __restrict__ xc)
{
    int idx = blockIdx.x * blockDim.x + threadIdx.x;
    if (idx >= TOK*DINNER) return;
    int t = idx / DINNER, d = idx % DINNER;
    int b = t / SEQ, n = t % SEQ;
    float acc = cb[d];
    #pragma unroll
    for (int k = 0; k < DCONV; k++) {
        int nn = n - (DCONV-1) + k;
        if (nn >= 0)
            acc += cw[d*DCONV + k] * xz[(size_t)(b*SEQ + nn)*(2*DINNER) + d];
    }
    xc[idx] = acc / (1.f + __expf(-acc));
}

// ---------------- K5: scan phase A (per-chunk carry, zero init) -------------
__global__ void scan_phaseA_kernel(const float* __restrict__ dbc,
                                   const float* __restrict__ xc,
                                   const float* __restrict__ A_log,
                                   float* __restrict__ carryP,
                                   float* __restrict__ carryF)
{
    __shared__ float sBC[CHUNK*32];
    int d = threadIdx.x;                 // 0..191
    int c = blockIdx.x;                  // chunk
    int b = blockIdx.y;
    int t0 = b*SEQ + c*CHUNK;
    for (int i = d; i < CHUNK*32; i += DINNER) {
        int tt = i >> 5, j = i & 31;
        sBC[i] = dbc[(size_t)(t0+tt)*XPROJ_OUT + DINNER + j];
    }
    float nA[DSTATE], h[DSTATE], ap[DSTATE];
    #pragma unroll
    for (int s = 0; s < DSTATE; s++) {
        nA[s] = -__expf(A_log[d*DSTATE + s]);
        h[s] = 0.f; ap[s] = 1.f;
    }
    __syncthreads();
    for (int t = 0; t < CHUNK; t++) {
        float dt  = dbc[(size_t)(t0+t)*XPROJ_OUT + d];
        float x   = xc [(size_t)(t0+t)*DINNER + d];
        float dtx = dt * x;
        const float* bc = &sBC[t*32];
        #pragma unroll
        for (int s = 0; s < DSTATE; s++) {
            float a = __expf(dt * nA[s]);
            h[s]  = a*h[s] + dtx*bc[s];
            ap[s] *= a;
        }
    }
    size_t base = ((size_t)(b*NCH + c)*DINNER + d)*DSTATE;
    #pragma unroll
    for (int s = 0; s < DSTATE; s++) { carryP[base+s] = ap[s]; carryF[base+s] = h[s]; }
}

// ---------------- K6: scan phase B (sequential carry combine) ---------------
__global__ void scan_phaseB_kernel(const float* __restrict__ carryP,
                                   const float* __restrict__ carryF,
                                   float* __restrict__ hinit)
{
    int idx = blockIdx.x * blockDim.x + threadIdx.x;
    if (idx >= BSZ*DINNER*DSTATE) return;
    int b  = idx / (DINNER*DSTATE);
    int ds = idx % (DINNER*DSTATE);
    float h = 0.f;
    for (int c = 0; c < NCH; c++) {
        size_t o = (size_t)(b*NCH + c)*(DINNER*DSTATE) + ds;
        hinit[o] = h;
        h = carryF[o] + carryP[o]*h;
    }
}

// ---------------- K7: scan phase C (final scan + y + D skip + silu(z) gate) -
__global__ void scan_phaseC_kernel(const float* __restrict__ dbc,
                                   const float* __restrict__ xc,
                                   const float* __restrict__ xz,
                                   const float* __restrict__ A_log,
                                   const float* __restrict__ Dp,
                                   const float* __restrict__ hinit,
                                   float* __restrict__ yg)
{
    __shared__ float sBC[CHUNK*32];
    int d = threadIdx.x;
    int c = blockIdx.x;
    int b = blockIdx.y;
    int t0 = b*SEQ + c*CHUNK;
    for (int i = d; i < CHUNK*32; i += DINNER) {
        int tt = i >> 5, j = i & 31;
        sBC[i] = dbc[(size_t)(t0+tt)*XPROJ_OUT + DINNER + j];
    }
    float nA[DSTATE], h[DSTATE];
    size_t hb = (size_t)(b*NCH + c)*(DINNER*DSTATE) + d*DSTATE;
    #pragma unroll
    for (int s = 0; s < DSTATE; s++) {
        nA[s] = -__expf(A_log[d*DSTATE + s]);
        h[s]  = hinit[hb + s];
    }
    float Dd = Dp[d];
    __syncthreads();
    for (int t = 0; t < CHUNK; t++) {
        float dt  = dbc[(size_t)(t0+t)*XPROJ_OUT + d];
        float x   = xc [(size_t)(t0+t)*DINNER + d];
        float dtx = dt * x;
        const float* bc = &sBC[t*32];
        float y = 0.f;
        #pragma unroll
        for (int s = 0; s < DSTATE; s++) {
            float a = __expf(dt * nA[s]);
            h[s] = a*h[s] + dtx*bc[s];
            y += h[s] * bc[16 + s];
        }
        float yv = y + x*Dd;
        float z  = xz[(size_t)(t0+t)*(2*DINNER) + DINNER + d];
        yg[(size_t)(t0+t)*DINNER + d] = yv * (z / (1.f + __expf(-z)));
    }
}

// ---------------- launch -----------------------------------------------------
extern "C" void kernel_launch(void* const* d_in, const int* in_sizes, int n_in,
                              void* d_out, int out_size)
{
    const float* x1   = (const float*)d_in[0];
    const float* x2   = (const float*)d_in[1];
    const float* ln1g = (const float*)d_in[2];
    const float* ln1b = (const float*)d_in[3];
    const float* ln2g = (const float*)d_in[4];
    const float* ln2b = (const float*)d_in[5];

    float *xs1, *xs2, *xz, *xc, *dbc, *w2, *cP, *cF, *hin, *yg;
    cudaGetSymbolAddress((void**)&xs1, g_xs1);
    cudaGetSymbolAddress((void**)&xs2, g_xs2);
    cudaGetSymbolAddress((void**)&xz,  g_xz);
    cudaGetSymbolAddress((void**)&xc,  g_xc);
    cudaGetSymbolAddress((void**)&dbc, g_dbc);
    cudaGetSymbolAddress((void**)&w2,  g_w2);
    cudaGetSymbolAddress((void**)&cP,  g_carryP);
    cudaGetSymbolAddress((void**)&cF,  g_carryF);
    cudaGetSymbolAddress((void**)&hin, g_hinit);
    cudaGetSymbolAddress((void**)&yg,  g_yg);

    // K1: layernorm + swap + shuffle (produces inputs for both mambas)
    ln_swap_shuffle_kernel<<<TOK/8, 256>>>(x1, x2, ln1g, ln1b, ln2g, ln2b, xs1, xs2);

    for (int mi = 0; mi < 2; mi++) {
        int base = 6 + mi*9;
        const float* in_w    = (const float*)d_in[base + 0];  // [384,96]
        const float* conv_w  = (const float*)d_in[base + 1];  // [192,4]
        const float* conv_b  = (const float*)d_in[base + 2];  // [192]
        const float* xproj_w = (const float*)d_in[base + 3];  // [38,192]
        const float* dt_w    = (const float*)d_in[base + 4];  // [192,6]
        const float* dt_b    = (const float*)d_in[base + 5];  // [192]
        const float* A_log   = (const float*)d_in[base + 6];  // [192,16]
        const float* Dp      = (const float*)d_in[base + 7];  // [192]
        const float* out_w   = (const float*)d_in[base + 8];  // [96,192]
        const float* xs      = mi == 0 ? xs1 : xs2;
        const float* resid   = mi == 0 ? x1 : x2;
        float* outp = (float*)d_out + (size_t)mi * TOK * DIMC;

        // fold xproj/dt projections
        prep_w2_kernel<<<(XPROJ_OUT*DINNER + 255)/256, 256>>>(xproj_w, dt_w, w2);

        // in_proj: xz = xs @ in_w^T   [12800,96]x[384,96]^T
        {
            dim3 grid(TOK/64, (2*DINNER + 63)/64);
            gemm_kernel<0><<<grid, 256>>>(xs, in_w, xz, TOK, 2*DINNER, DIMC, nullptr, nullptr);
        }
        // depthwise conv + silu
        conv_silu_kernel<<<(TOK*DINNER + 255)/256, 256>>>(xz, conv_w, conv_b, xc);
        // fused xproj+dtproj: dbc = [softplus(xc@Wdt^T+dt_b) | B | C]
        {
            dim3 grid(TOK/64, (XPROJ_OUT + 63)/64);
            gemm_kernel<1><<<grid, 256>>>(xc, w2, dbc, TOK, XPROJ_OUT, DINNER, dt_b, nullptr);
        }
        // chunked parallel scan
        {
            dim3 grid(NCH, BSZ);
            scan_phaseA_kernel<<<grid, DINNER>>>(dbc, xc, A_log, cP, cF);
            scan_phaseB_kernel<<<(BSZ*DINNER*DSTATE + 255)/256, 256>>>(cP, cF, hin);
            scan_phaseC_kernel<<<grid, DINNER>>>(dbc, xc, xz, A_log, Dp, hin, yg);
        }
        // out_proj + residual
        {
            dim3 grid(TOK/64, (DIMC + 63)/64);
            gemm_kernel<2><<<grid, 256>>>(yg, out_w, outp, TOK, DIMC, DINNER, nullptr, resid);
        }
    }
}

// round 2
// speedup vs baseline: 1.1525x; 1.1525x over previous
#include <cuda_runtime.h>
#include <cuda_bf16.h>
#include <math.h>

#define DIMC   96
#define DINNER 192
#define DSTATE 16
#define DCONV  4
#define DTRANK 6
#define NSWAP  59
#define BSZ    2
#define SEQ    6400
#define TOK    (BSZ*SEQ)     // 12800
#define CHUNK  32
#define NCH    (SEQ/CHUNK)   // 200
#define XPROJ_OUT 224        // 192 dt + 16 B + 16 C
#define CARRY_PER_Z (BSZ*NCH*DINNER*DSTATE)   // 2*200*3072 = 1,228,800

// ---------------- scratch (static device globals; no allocation) ------------
__device__ __align__(16) float g_xs [2*TOK*DIMC];
__device__ __align__(16) float g_xz [2*TOK*2*DINNER];
__device__ __align__(16) float g_xc [2*TOK*DINNER];
__device__ __align__(16) float g_dbc[2*TOK*XPROJ_OUT];
__device__ __align__(16) float g_w2 [2*XPROJ_OUT*DINNER];
__device__ __align__(16) float g_carryP[2*CARRY_PER_Z];
__device__ __align__(16) float g_carryF[2*CARRY_PER_Z];
__device__ __align__(16) float g_hinit [2*CARRY_PER_Z];
__device__ __align__(16) float g_yg [2*TOK*DINNER];

// ---------------- K0: fold dt_w @ xproj_w[:6] and pack B/C rows (both z) ----
__global__ void prep_w2_kernel(const float* __restrict__ xp0, const float* __restrict__ dw0,
                               const float* __restrict__ xp1, const float* __restrict__ dw1,
                               float* __restrict__ w2)
{
    int idx = blockIdx.x * blockDim.x + threadIdx.x;
    if (idx >= 2*XPROJ_OUT*DINNER) return;
    int z = idx / (XPROJ_OUT*DINNER);
    int e = idx % (XPROJ_OUT*DINNER);
    const float* xproj = z ? xp1 : xp0;
    const float* dtw   = z ? dw1 : dw0;
    int r = e / DINNER, c = e % DINNER;
    float v;
    if (r < DINNER) {
        v = 0.f;
        #pragma unroll
        for (int j = 0; j < DTRANK; j++)
            v += dtw[r*DTRANK + j] * xproj[j*DINNER + c];
    } else if (r < DINNER + DSTATE) {
        v = xproj[(DTRANK + (r - DINNER))*DINNER + c];
    } else {
        v = xproj[(DTRANK + DSTATE + (r - DINNER - DSTATE))*DINNER + c];
    }
    w2[idx] = v;
}

// ---------------- K1: layernorm + token-swap + channel shuffle --------------
__global__ void ln_swap_shuffle_kernel(const float* __restrict__ x1,
                                       const float* __restrict__ x2,
                                       const float* __restrict__ g1, const float* __restrict__ b1,
                                       const float* __restrict__ g2, const float* __restrict__ b2,
                                       float* __restrict__ xs)
{
    __shared__ float s1[8][DIMC];
    __shared__ float s2[8][DIMC];
    int w = threadIdx.x >> 5, lane = threadIdx.x & 31;
    int token = blockIdx.x * 8 + w;       // TOK divisible by 8
    const float* p1 = x1 + (size_t)token*DIMC;
    const float* p2 = x2 + (size_t)token*DIMC;
    float a0 = p1[lane], a1 = p1[lane+32], a2 = p1[lane+64];
    float c0 = p2[lane], c1 = p2[lane+32], c2 = p2[lane+64];
    float sum1 = a0+a1+a2, sq1 = a0*a0+a1*a1+a2*a2;
    float sum2 = c0+c1+c2, sq2 = c0*c0+c1*c1+c2*c2;
    #pragma unroll
    for (int o = 16; o > 0; o >>= 1) {
        sum1 += __shfl_xor_sync(0xffffffffu, sum1, o);
        sq1  += __shfl_xor_sync(0xffffffffu, sq1,  o);
        sum2 += __shfl_xor_sync(0xffffffffu, sum2, o);
        sq2  += __shfl_xor_sync(0xffffffffu, sq2,  o);
    }
    float m1 = sum1 * (1.f/DIMC), v1 = sq1 * (1.f/DIMC) - m1*m1;
    float m2 = sum2 * (1.f/DIMC), v2 = sq2 * (1.f/DIMC) - m2*m2;
    float r1 = rsqrtf(v1 + 1e-5f), r2 = rsqrtf(v2 + 1e-5f);
    #pragma unroll
    for (int k = 0; k < 3; k++) {
        int ch = lane + 32*k;
        float xv = (k==0? a0 : k==1? a1 : a2);
        float yv = (k==0? c0 : k==1? c1 : c2);
        s1[w][ch] = (xv - m1) * r1 * g1[ch] + b1[ch];
        s2[w][ch] = (yv - m2) * r2 * g2[ch] + b2[ch];
    }
    __syncwarp();
    #pragma unroll
    for (int k = 0; k < 3; k++) {
        int ch  = lane + 32*k;
        int src = (ch & 1)*48 + (ch >> 1);        // channel shuffle (groups=2)
        float p2v = s2[w][src];                   // x2s == shuffled x2n
        float p1v = (src < NSWAP) ? s2[w][src] : s1[w][src];
        xs[(size_t)token*DIMC + ch]                     = p1v;
        xs[(size_t)(TOK + token)*DIMC + ch]             = p2v;
    }
}

// ---------------- K2: register-tiled fp32 GEMM: out = A[M,K] @ W[N,K]^T -----
// 128x64 tile, 8x4 per thread, BK=32. z = mamba index.
// MODE 0: plain   MODE 1: softplus(v+bias[col]) for col<192   MODE 2: +resid
#define BM 128
#define BN 64
#define BK 32

template<int MODE>
__global__ void __launch_bounds__(256, 3)
gemm_kernel(const float* __restrict__ A0, const float* __restrict__ A1,
            const float* __restrict__ W0, const float* __restrict__ W1,
            float* __restrict__ O0, float* __restrict__ O1,
            int M, int N, int K,
            const float* __restrict__ bi0, const float* __restrict__ bi1,
            const float* __restrict__ rs0, const float* __restrict__ rs1)
{
    __shared__ float sA[BM][BK+4];   // 128 x 36 (16B-aligned rows)
    __shared__ float sB[BK][BN+4];   // 32 x 68
    int z = blockIdx.z;
    const float* A     = z ? A1 : A0;
    const float* W     = z ? W1 : W0;
    float*       O     = z ? O1 : O0;
    const float* bias  = z ? bi1 : bi0;
    const float* resid = z ? rs1 : rs0;

    int tid = threadIdx.x;
    int tx = tid & 15;         // col group (4 cols)
    int ty = tid >> 4;         // row group (8 rows)
    int m0 = blockIdx.x * BM;
    int n0 = blockIdx.y * BN;

    float acc[8][4] = {};
    for (int k0 = 0; k0 < K; k0 += BK) {
        #pragma unroll
        for (int p = 0; p < 4; p++) {           // A tile: 128x32
            int idx = tid + p*256;
            int r = idx >> 3, f = (idx & 7) << 2;
            float4 v = *reinterpret_cast<const float4*>(A + (size_t)(m0+r)*K + k0 + f);
            *reinterpret_cast<float4*>(&sA[r][f]) = v;
        }
        #pragma unroll
        for (int p = 0; p < 2; p++) {           // B tile: 64x32, transpose
            int idx = tid + p*256;
            int n = idx >> 3, f = (idx & 7) << 2;
            float4 v = make_float4(0.f,0.f,0.f,0.f);
            if (n0 + n < N)
                v = *reinterpret_cast<const float4*>(W + (size_t)(n0+n)*K + k0 + f);
            sB[f+0][n] = v.x; sB[f+1][n] = v.y; sB[f+2][n] = v.z; sB[f+3][n] = v.w;
        }
        __syncthreads();
        #pragma unroll
        for (int kk = 0; kk < BK; kk++) {
            float4 bv = *reinterpret_cast<const float4*>(&sB[kk][tx<<2]);
            float a[8];
            #pragma unroll
            for (int i = 0; i < 8; i++) a[i] = sA[(ty<<3)+i][kk];
            #pragma unroll
            for (int i = 0; i < 8; i++) {
                acc[i][0] += a[i]*bv.x;
                acc[i][1] += a[i]*bv.y;
                acc[i][2] += a[i]*bv.z;
                acc[i][3] += a[i]*bv.w;
            }
        }
        __syncthreads();
    }

    bool full = (n0 + BN <= N);
    #pragma unroll
    for (int i = 0; i < 8; i++) {
        int row = m0 + (ty<<3) + i;
        int col = n0 + (tx<<2);
        float v[4] = {acc[i][0], acc[i][1], acc[i][2], acc[i][3]};
        if (MODE == 1) {
            #pragma unroll
            for (int j = 0; j < 4; j++) {
                if (col + j < DINNER) {
                    float t = v[j] + bias[col+j];
                    v[j] = (t > 20.f) ? t : log1pf(__expf(t));
                }
            }
        } else if (MODE == 2) {
            #pragma unroll
            for (int j = 0; j < 4; j++)
                if (col + j < N) v[j] += resid[(size_t)row*N + col + j];
        }
        if (full) {
            float4 o = make_float4(v[0], v[1], v[2], v[3]);
            *reinterpret_cast<float4*>(O + (size_t)row*N + col) = o;
        } else {
            #pragma unroll
            for (int j = 0; j < 4; j++)
                if (col + j < N) O[(size_t)row*N + col + j] = v[j];
        }
    }
}

// ---------------- K3: depthwise causal conv(4) + silu (float4, both z) ------
__global__ void conv_silu_kernel(const float* __restrict__ xz,
                                 const float* __restrict__ cw0, const float* __restrict__ cw1,
                                 const float* __restrict__ cb0, const float* __restrict__ cb1,
                                 float* __restrict__ xc)
{
    int z = blockIdx.z;
    const float* cw = z ? cw1 : cw0;
    const float* cb = z ? cb1 : cb0;
    const float* xzp = xz + (size_t)z*TOK*2*DINNER;
    float*       xcp = xc + (size_t)z*TOK*DINNER;

    int e = blockIdx.x * blockDim.x + threadIdx.x;    // over TOK*48
    if (e >= TOK*(DINNER/4)) return;
    int t = e / (DINNER/4), q = e % (DINNER/4);
    int d = q * 4;
    int b = t / SEQ, n = t % SEQ;
    float4 acc = *reinterpret_cast<const float4*>(cb + d);
    #pragma unroll
    for (int k = 0; k < DCONV; k++) {
        int nn = n - (DCONV-1) + k;
        if (nn >= 0) {
            float4 xv = *reinterpret_cast<const float4*>(xzp + (size_t)(b*SEQ+nn)*(2*DINNER) + d);
            acc.x += cw[(d+0)*DCONV + k] * xv.x;
            acc.y += cw[(d+1)*DCONV + k] * xv.y;
            acc.z += cw[(d+2)*DCONV + k] * xv.z;
            acc.w += cw[(d+3)*DCONV + k] * xv.w;
        }
    }
    acc.x = acc.x / (1.f + __expf(-acc.x));
    acc.y = acc.y / (1.f + __expf(-acc.y));
    acc.z = acc.z / (1.f + __expf(-acc.z));
    acc.w = acc.w / (1.f + __expf(-acc.w));
    *reinterpret_cast<float4*>(xcp + (size_t)t*DINNER + d) = acc;
}

// ---------------- K5: scan phase A (per-chunk carry, zero init) -------------
__global__ void scan_phaseA_kernel(const float* __restrict__ dbc_,
                                   const float* __restrict__ xc_,
                                   const float* __restrict__ Al0, const float* __restrict__ Al1,
                                   float* __restrict__ carryP_,
                                   float* __restrict__ carryF_)
{
    __shared__ float sBC[CHUNK*32];
    int z = blockIdx.z;
    const float* A_log = z ? Al1 : Al0;
    const float* dbc = dbc_ + (size_t)z*TOK*XPROJ_OUT;
    const float* xc  = xc_  + (size_t)z*TOK*DINNER;
    float* carryP = carryP_ + (size_t)z*CARRY_PER_Z;
    float* carryF = carryF_ + (size_t)z*CARRY_PER_Z;

    int d = threadIdx.x;                 // 0..191
    int c = blockIdx.x;                  // chunk
    int b = blockIdx.y;
    int t0 = b*SEQ + c*CHUNK;
    for (int i = d; i < CHUNK*32; i += DINNER) {
        int tt = i >> 5, j = i & 31;
        sBC[i] = dbc[(size_t)(t0+tt)*XPROJ_OUT + DINNER + j];
    }
    float nA[DSTATE], h[DSTATE], ap[DSTATE];
    #pragma unroll
    for (int s = 0; s < DSTATE; s++) {
        nA[s] = -__expf(A_log[d*DSTATE + s]);
        h[s] = 0.f; ap[s] = 1.f;
    }
    __syncthreads();
    #pragma unroll 4
    for (int t = 0; t < CHUNK; t++) {
        float dt  = dbc[(size_t)(t0+t)*XPROJ_OUT + d];
        float x   = xc [(size_t)(t0+t)*DINNER + d];
        float dtx = dt * x;
        const float* bc = &sBC[t*32];
        #pragma unroll
        for (int s = 0; s < DSTATE; s++) {
            float a = __expf(dt * nA[s]);
            h[s]  = a*h[s] + dtx*bc[s];
            ap[s] *= a;
        }
    }
    size_t base = ((size_t)z*CARRY_PER_Z) ? 0 : 0;  // (offset already applied)
    size_t o = ((size_t)(b*NCH + c)*DINNER + d)*DSTATE;
    #pragma unroll
    for (int s = 0; s < DSTATE; s++) { carryP[o+s] = ap[s]; carryF[o+s] = h[s]; }
    (void)base;
}

// ---------------- K6: scan phase B (sequential carry combine) ---------------
__global__ void scan_phaseB_kernel(const float* __restrict__ carryP,
                                   const float* __restrict__ carryF,
                                   float* __restrict__ hinit)
{
    int idx = blockIdx.x * blockDim.x + threadIdx.x;
    if (idx >= 2*BSZ*DINNER*DSTATE) return;
    int z  = idx / (BSZ*DINNER*DSTATE);
    int r  = idx % (BSZ*DINNER*DSTATE);
    int b  = r / (DINNER*DSTATE);
    int ds = r % (DINNER*DSTATE);
    size_t zoff = (size_t)z*CARRY_PER_Z;
    float h = 0.f;
    for (int c = 0; c < NCH; c++) {
        size_t o = zoff + (size_t)(b*NCH + c)*(DINNER*DSTATE) + ds;
        hinit[o] = h;
        h = carryF[o] + carryP[o]*h;
    }
}

// ---------------- K7: scan phase C (final scan + y + D skip + silu(z) gate) -
__global__ void scan_phaseC_kernel(const float* __restrict__ dbc_,
                                   const float* __restrict__ xc_,
                                   const float* __restrict__ xz_,
                                   const float* __restrict__ Al0, const float* __restrict__ Al1,
                                   const float* __restrict__ Dp0, const float* __restrict__ Dp1,
                                   const float* __restrict__ hinit_,
                                   float* __restrict__ yg_)
{
    __shared__ float sBC[CHUNK*32];
    int z = blockIdx.z;
    const float* A_log = z ? Al1 : Al0;
    const float* Dp    = z ? Dp1 : Dp0;
    const float* dbc = dbc_ + (size_t)z*TOK*XPROJ_OUT;
    const float* xc  = xc_  + (size_t)z*TOK*DINNER;
    const float* xz  = xz_  + (size_t)z*TOK*2*DINNER;
    const float* hinit = hinit_ + (size_t)z*CARRY_PER_Z;
    float* yg = yg_ + (size_t)z*TOK*DINNER;

    int d = threadIdx.x;
    int c = blockIdx.x;
    int b = blockIdx.y;
    int t0 = b*SEQ + c*CHUNK;
    for (int i = d; i < CHUNK*32; i += DINNER) {
        int tt = i >> 5, j = i & 31;
        sBC[i] = dbc[(size_t)(t0+tt)*XPROJ_OUT + DINNER + j];
    }
    float nA[DSTATE], h[DSTATE];
    size_t hb = (size_t)(b*NCH + c)*(DINNER*DSTATE) + d*DSTATE;
    #pragma unroll
    for (int s = 0; s < DSTATE; s++) {
        nA[s] = -__expf(A_log[d*DSTATE + s]);
        h[s]  = hinit[hb + s];
    }
    float Dd = Dp[d];
    __syncthreads();
    #pragma unroll 4
    for (int t = 0; t < CHUNK; t++) {
        float dt  = dbc[(size_t)(t0+t)*XPROJ_OUT + d];
        float x   = xc [(size_t)(t0+t)*DINNER + d];
        float dtx = dt * x;
        const float* bc = &sBC[t*32];
        float y = 0.f;
        #pragma unroll
        for (int s = 0; s < DSTATE; s++) {
            float a = __expf(dt * nA[s]);
            h[s] = a*h[s] + dtx*bc[s];
            y += h[s] * bc[16 + s];
        }
        float yv = y + x*Dd;
        float zz = xz[(size_t)(t0+t)*(2*DINNER) + DINNER + d];
        yg[(size_t)(t0+t)*DINNER + d] = yv * (zz / (1.f + __expf(-zz)));
    }
}

// ---------------- launch -----------------------------------------------------
extern "C" void kernel_launch(void* const* d_in, const int* in_sizes, int n_in,
                              void* d_out, int out_size)
{
    const float* x1   = (const float*)d_in[0];
    const float* x2   = (const float*)d_in[1];
    const float* ln1g = (const float*)d_in[2];
    const float* ln1b = (const float*)d_in[3];
    const float* ln2g = (const float*)d_in[4];
    const float* ln2b = (const float*)d_in[5];

    const float* in_w[2], *conv_w[2], *conv_b[2], *xproj_w[2], *dt_w[2],
               * dt_b[2], *A_log[2], *Dp[2], *out_w[2];
    for (int mi = 0; mi < 2; mi++) {
        int base = 6 + mi*9;
        in_w[mi]    = (const float*)d_in[base + 0];
        conv_w[mi]  = (const float*)d_in[base + 1];
        conv_b[mi]  = (const float*)d_in[base + 2];
        xproj_w[mi] = (const float*)d_in[base + 3];
        dt_w[mi]    = (const float*)d_in[base + 4];
        dt_b[mi]    = (const float*)d_in[base + 5];
        A_log[mi]   = (const float*)d_in[base + 6];
        Dp[mi]      = (const float*)d_in[base + 7];
        out_w[mi]   = (const float*)d_in[base + 8];
    }

    float *xs, *xz, *xc, *dbc, *w2, *cP, *cF, *hin, *yg;
    cudaGetSymbolAddress((void**)&xs,  g_xs);
    cudaGetSymbolAddress((void**)&xz,  g_xz);
    cudaGetSymbolAddress((void**)&xc,  g_xc);
    cudaGetSymbolAddress((void**)&dbc, g_dbc);
    cudaGetSymbolAddress((void**)&w2,  g_w2);
    cudaGetSymbolAddress((void**)&cP,  g_carryP);
    cudaGetSymbolAddress((void**)&cF,  g_carryF);
    cudaGetSymbolAddress((void**)&hin, g_hinit);
    cudaGetSymbolAddress((void**)&yg,  g_yg);

    float* out0 = (float*)d_out;
    float* out1 = (float*)d_out + (size_t)TOK*DIMC;

    // K1: layernorm + swap + shuffle  (fills both halves of g_xs)
    ln_swap_shuffle_kernel<<<TOK/8, 256>>>(x1, x2, ln1g, ln1b, ln2g, ln2b, xs);

    // K0: fold xproj/dt weights (both mambas)
    prep_w2_kernel<<<(2*XPROJ_OUT*DINNER + 255)/256, 256>>>(
        xproj_w[0], dt_w[0], xproj_w[1], dt_w[1], w2);

    // in_proj: xz = xs @ in_w^T   [12800,96]x[384,96]^T, both z
    {
        dim3 grid(TOK/BM, (2*DINNER + BN - 1)/BN, 2);
        gemm_kernel<0><<<grid, 256>>>(
            xs, xs + (size_t)TOK*DIMC,
            in_w[0], in_w[1],
            xz, xz + (size_t)TOK*2*DINNER,
            TOK, 2*DINNER, DIMC,
            nullptr, nullptr, nullptr, nullptr);
    }

    // depthwise conv + silu, both z
    {
        dim3 grid((TOK*(DINNER/4) + 255)/256, 1, 2);
        conv_silu_kernel<<<grid, 256>>>(xz, conv_w[0], conv_w[1], conv_b[0], conv_b[1], xc);
    }

    // fused xproj+dtproj: dbc = [softplus(xc@Wdt^T+dt_b) | B | C], both z
    {
        dim3 grid(TOK/BM, (XPROJ_OUT + BN - 1)/BN, 2);
        gemm_kernel<1><<<grid, 256>>>(
            xc, xc + (size_t)TOK*DINNER,
            w2, w2 + (size_t)XPROJ_OUT*DINNER,
            dbc, dbc + (size_t)TOK*XPROJ_OUT,
            TOK, XPROJ_OUT, DINNER,
            dt_b[0], dt_b[1], nullptr, nullptr);
    }

    // chunked parallel scan, both z
    {
        dim3 grid(NCH, BSZ, 2);
        scan_phaseA_kernel<<<grid, DINNER>>>(dbc, xc, A_log[0], A_log[1], cP, cF);
        scan_phaseB_kernel<<<(2*BSZ*DINNER*DSTATE + 255)/256, 256>>>(cP, cF, hin);
        scan_phaseC_kernel<<<grid, DINNER>>>(dbc, xc, xz, A_log[0], A_log[1],
                                             Dp[0], Dp[1], hin, yg);
    }

    // out_proj + residual, both z
    {
        dim3 grid(TOK/BM, (DIMC + BN - 1)/BN, 2);
        gemm_kernel<2><<<grid, 256>>>(
            yg, yg + (size_t)TOK*DINNER,
            out_w[0], out_w[1],
            out0, out1,
            TOK, DIMC, DINNER,
            nullptr, nullptr, x1, x2);
    }
}

// round 3
// speedup vs baseline: 1.1849x; 1.0281x over previous
#include <cuda_runtime.h>
#include <cuda_bf16.h>
#include <math.h>

#define DIMC   96
#define DINNER 192
#define DSTATE 16
#define DCONV  4
#define DTRANK 6
#define NSWAP  59
#define BSZ    2
#define SEQ    6400
#define TOK    (BSZ*SEQ)     // 12800
#define CHUNK  32
#define NCH    (SEQ/CHUNK)   // 200
#define XPROJ_OUT 224        // 192 dt + 16 B + 16 C
#define CARRY_PER_Z (BSZ*NCH*DINNER*DSTATE)

// ---------------- scratch (static device globals; no allocation) ------------
__device__ __align__(16) float g_xs [2*TOK*DIMC];
__device__ __align__(16) float g_xz [2*TOK*2*DINNER];
__device__ __align__(16) float g_xc [2*TOK*DINNER];
__device__ __align__(16) float g_dbc[2*TOK*XPROJ_OUT];
__device__ __align__(16) float g_w2 [2*XPROJ_OUT*DINNER];
__device__ __align__(16) float g_carryP[2*CARRY_PER_Z];
__device__ __align__(16) float g_carryF[2*CARRY_PER_Z];
__device__ __align__(16) float g_hinit [2*CARRY_PER_Z];
__device__ __align__(16) float g_yg [2*TOK*DINNER];

// ---------------- K0: fold dt_w @ xproj_w[:6] and pack B/C rows (both z) ----
__global__ void prep_w2_kernel(const float* __restrict__ xp0, const float* __restrict__ dw0,
                               const float* __restrict__ xp1, const float* __restrict__ dw1,
                               float* __restrict__ w2)
{
    int idx = blockIdx.x * blockDim.x + threadIdx.x;
    if (idx >= 2*XPROJ_OUT*DINNER) return;
    int z = idx / (XPROJ_OUT*DINNER);
    int e = idx % (XPROJ_OUT*DINNER);
    const float* xproj = z ? xp1 : xp0;
    const float* dtw   = z ? dw1 : dw0;
    int r = e / DINNER, c = e % DINNER;
    float v;
    if (r < DINNER) {
        v = 0.f;
        #pragma unroll
        for (int j = 0; j < DTRANK; j++)
            v += dtw[r*DTRANK + j] * xproj[j*DINNER + c];
    } else if (r < DINNER + DSTATE) {
        v = xproj[(DTRANK + (r - DINNER))*DINNER + c];
    } else {
        v = xproj[(DTRANK + DSTATE + (r - DINNER - DSTATE))*DINNER + c];
    }
    w2[idx] = v;
}

// ---------------- K1: layernorm + token-swap + channel shuffle --------------
__global__ void ln_swap_shuffle_kernel(const float* __restrict__ x1,
                                       const float* __restrict__ x2,
                                       const float* __restrict__ g1, const float* __restrict__ b1,
                                       const float* __restrict__ g2, const float* __restrict__ b2,
                                       float* __restrict__ xs)
{
    __shared__ float s1[8][DIMC];
    __shared__ float s2[8][DIMC];
    int w = threadIdx.x >> 5, lane = threadIdx.x & 31;
    int token = blockIdx.x * 8 + w;
    const float* p1 = x1 + (size_t)token*DIMC;
    const float* p2 = x2 + (size_t)token*DIMC;
    float a0 = p1[lane], a1 = p1[lane+32], a2 = p1[lane+64];
    float c0 = p2[lane], c1 = p2[lane+32], c2 = p2[lane+64];
    float sum1 = a0+a1+a2, sq1 = a0*a0+a1*a1+a2*a2;
    float sum2 = c0+c1+c2, sq2 = c0*c0+c1*c1+c2*c2;
    #pragma unroll
    for (int o = 16; o > 0; o >>= 1) {
        sum1 += __shfl_xor_sync(0xffffffffu, sum1, o);
        sq1  += __shfl_xor_sync(0xffffffffu, sq1,  o);
        sum2 += __shfl_xor_sync(0xffffffffu, sum2, o);
        sq2  += __shfl_xor_sync(0xffffffffu, sq2,  o);
    }
    float m1 = sum1 * (1.f/DIMC), v1 = sq1 * (1.f/DIMC) - m1*m1;
    float m2 = sum2 * (1.f/DIMC), v2 = sq2 * (1.f/DIMC) - m2*m2;
    float r1 = rsqrtf(v1 + 1e-5f), r2 = rsqrtf(v2 + 1e-5f);
    #pragma unroll
    for (int k = 0; k < 3; k++) {
        int ch = lane + 32*k;
        float xv = (k==0? a0 : k==1? a1 : a2);
        float yv = (k==0? c0 : k==1? c1 : c2);
        s1[w][ch] = (xv - m1) * r1 * g1[ch] + b1[ch];
        s2[w][ch] = (yv - m2) * r2 * g2[ch] + b2[ch];
    }
    __syncwarp();
    #pragma unroll
    for (int k = 0; k < 3; k++) {
        int ch  = lane + 32*k;
        int src = (ch & 1)*48 + (ch >> 1);        // channel shuffle (groups=2)
        float p2v = s2[w][src];                   // x2s == shuffled x2n
        float p1v = (src < NSWAP) ? s2[w][src] : s1[w][src];
        xs[(size_t)token*DIMC + ch]         = p1v;
        xs[(size_t)(TOK + token)*DIMC + ch] = p2v;
    }
}

// ---------------- K2: register-tiled fp32 GEMM: out = A[M,K] @ W[N,K]^T -----
#define BM 128
#define BN 64
#define BK 32

template<int MODE, int K>
__global__ void __launch_bounds__(256, 3)
gemm_kernel(const float* __restrict__ A0, const float* __restrict__ A1,
            const float* __restrict__ W0, const float* __restrict__ W1,
            float* __restrict__ O0, float* __restrict__ O1,
            int N,
            const float* __restrict__ bi0, const float* __restrict__ bi1,
            const float* __restrict__ rs0, const float* __restrict__ rs1)
{
    __shared__ float sA[BM][BK+4];
    __shared__ float sB[BK][BN+4];
    int z = blockIdx.z;
    const float* A     = z ? A1 : A0;
    const float* W     = z ? W1 : W0;
    float*       O     = z ? O1 : O0;
    const float* bias  = z ? bi1 : bi0;
    const float* resid = z ? rs1 : rs0;

    int tid = threadIdx.x;
    int tx = tid & 15;
    int ty = tid >> 4;
    int m0 = blockIdx.x * BM;
    int n0 = blockIdx.y * BN;

    float acc[8][4] = {};
    #pragma unroll
    for (int k0 = 0; k0 < K; k0 += BK) {
        #pragma unroll
        for (int p = 0; p < 4; p++) {
            int idx = tid + p*256;
            int r = idx >> 3, f = (idx & 7) << 2;
            float4 v = *reinterpret_cast<const float4*>(A + (size_t)(m0+r)*K + k0 + f);
            *reinterpret_cast<float4*>(&sA[r][f]) = v;
        }
        #pragma unroll
        for (int p = 0; p < 2; p++) {
            int idx = tid + p*256;
            int n = idx >> 3, f = (idx & 7) << 2;
            float4 v = make_float4(0.f,0.f,0.f,0.f);
            if (n0 + n < N)
                v = *reinterpret_cast<const float4*>(W + (size_t)(n0+n)*K + k0 + f);
            sB[f+0][n] = v.x; sB[f+1][n] = v.y; sB[f+2][n] = v.z; sB[f+3][n] = v.w;
        }
        __syncthreads();
        #pragma unroll
        for (int kk = 0; kk < BK; kk++) {
            float4 bv = *reinterpret_cast<const float4*>(&sB[kk][tx<<2]);
            float a[8];
            #pragma unroll
            for (int i = 0; i < 8; i++) a[i] = sA[(ty<<3)+i][kk];
            #pragma unroll
            for (int i = 0; i < 8; i++) {
                acc[i][0] += a[i]*bv.x;
                acc[i][1] += a[i]*bv.y;
                acc[i][2] += a[i]*bv.z;
                acc[i][3] += a[i]*bv.w;
            }
        }
        __syncthreads();
    }

    bool full = (n0 + BN <= N);
    #pragma unroll
    for (int i = 0; i < 8; i++) {
        int row = m0 + (ty<<3) + i;
        int col = n0 + (tx<<2);
        float v[4] = {acc[i][0], acc[i][1], acc[i][2], acc[i][3]};
        if (MODE == 1) {
            #pragma unroll
            for (int j = 0; j < 4; j++) {
                if (col + j < DINNER) {
                    float t = v[j] + bias[col+j];
                    v[j] = (t > 20.f) ? t : log1pf(__expf(t));
                }
            }
        } else if (MODE == 2) {
            #pragma unroll
            for (int j = 0; j < 4; j++)
                if (col + j < N) v[j] += resid[(size_t)row*N + col + j];
        }
        if (full) {
            *reinterpret_cast<float4*>(O + (size_t)row*N + col) =
                make_float4(v[0], v[1], v[2], v[3]);
        } else {
            #pragma unroll
            for (int j = 0; j < 4; j++)
                if (col + j < N) O[(size_t)row*N + col + j] = v[j];
        }
    }
}

// ---------------- K3: depthwise causal conv(4)+silu, sliding window ---------
#define CTPB 16   // tokens per thread
__global__ void conv_silu_kernel(const float* __restrict__ xz,
                                 const float* __restrict__ cw0, const float* __restrict__ cw1,
                                 const float* __restrict__ cb0, const float* __restrict__ cb1,
                                 float* __restrict__ xc)
{
    int z = blockIdx.z;
    const float* cw = z ? cw1 : cw0;
    const float* cb = z ? cb1 : cb0;
    const float* xzp = xz + (size_t)z*TOK*2*DINNER;
    float*       xcp = xc + (size_t)z*TOK*DINNER;

    int tid = threadIdx.x;          // block = 192: 48 quads x 4 token-blocks
    int q   = tid % 48;
    int tb  = blockIdx.x * 4 + tid / 48;   // 0..399
    int b   = blockIdx.y;
    int t0  = tb * CTPB;
    int d   = q * 4;

    // weights/bias in registers (once)
    float w00=cw[(d+0)*4+0], w01=cw[(d+0)*4+1], w02=cw[(d+0)*4+2], w03=cw[(d+0)*4+3];
    float w10=cw[(d+1)*4+0], w11=cw[(d+1)*4+1], w12=cw[(d+1)*4+2], w13=cw[(d+1)*4+3];
    float w20=cw[(d+2)*4+0], w21=cw[(d+2)*4+1], w22=cw[(d+2)*4+2], w23=cw[(d+2)*4+3];
    float w30=cw[(d+3)*4+0], w31=cw[(d+3)*4+1], w32=cw[(d+3)*4+2], w33=cw[(d+3)*4+3];
    float4 bias = *reinterpret_cast<const float4*>(cb + d);

    const float* xrow = xzp + (size_t)(b*SEQ)*(2*DINNER) + d;
    float4 h0, h1, h2;   // tokens t-3, t-2, t-1
    {
        int tt = t0 - 3;
        h0 = (tt >= 0) ? *reinterpret_cast<const float4*>(xrow + (size_t)tt*(2*DINNER))
                       : make_float4(0.f,0.f,0.f,0.f);
        tt = t0 - 2;
        h1 = (tt >= 0) ? *reinterpret_cast<const float4*>(xrow + (size_t)tt*(2*DINNER))
                       : make_float4(0.f,0.f,0.f,0.f);
        tt = t0 - 1;
        h2 = (tt >= 0) ? *reinterpret_cast<const float4*>(xrow + (size_t)tt*(2*DINNER))
                       : make_float4(0.f,0.f,0.f,0.f);
    }
    #pragma unroll 4
    for (int t = t0; t < t0 + CTPB; t++) {
        float4 h3 = *reinterpret_cast<const float4*>(xrow + (size_t)t*(2*DINNER));
        float4 o;
        o.x = bias.x + w00*h0.x + w01*h1.x + w02*h2.x + w03*h3.x;
        o.y = bias.y + w10*h0.y + w11*h1.y + w12*h2.y + w13*h3.y;
        o.z = bias.z + w20*h0.z + w21*h1.z + w22*h2.z + w23*h3.z;
        o.w = bias.w + w30*h0.w + w31*h1.w + w32*h2.w + w33*h3.w;
        o.x = o.x / (1.f + __expf(-o.x));
        o.y = o.y / (1.f + __expf(-o.y));
        o.z = o.z / (1.f + __expf(-o.z));
        o.w = o.w / (1.f + __expf(-o.w));
        *reinterpret_cast<float4*>(xcp + (size_t)(b*SEQ + t)*DINNER + d) = o;
        h0 = h1; h1 = h2; h2 = h3;
    }
}

// helper: does this A_log row equal log(1..16)? (fast-path eligibility)
__device__ __forceinline__ bool alog_is_arange(const float* A_log, int d, float nA[DSTATE])
{
    bool fast = true;
    #pragma unroll
    for (int s = 0; s < DSTATE; s++) {
        nA[s] = -__expf(A_log[d*DSTATE + s]);
        fast = fast && (fabsf(nA[s] + (float)(s+1)) <= 1e-4f * (float)(s+1));
    }
    return fast;
}

// ---------------- K5: scan phase A (per-chunk carry, zero init) -------------
__global__ void scan_phaseA_kernel(const float* __restrict__ dbc_,
                                   const float* __restrict__ xc_,
                                   const float* __restrict__ Al0, const float* __restrict__ Al1,
                                   float* __restrict__ carryP_,
                                   float* __restrict__ carryF_)
{
    __shared__ float sBC[CHUNK*32];
    int z = blockIdx.z;
    const float* A_log = z ? Al1 : Al0;
    const float* dbc = dbc_ + (size_t)z*TOK*XPROJ_OUT;
    const float* xc  = xc_  + (size_t)z*TOK*DINNER;
    float* carryP = carryP_ + (size_t)z*CARRY_PER_Z;
    float* carryF = carryF_ + (size_t)z*CARRY_PER_Z;

    int d = threadIdx.x;
    int c = blockIdx.x;
    int b = blockIdx.y;
    int t0 = b*SEQ + c*CHUNK;
    for (int i = d; i < CHUNK*32; i += DINNER) {
        int tt = i >> 5, j = i & 31;
        sBC[i] = dbc[(size_t)(t0+tt)*XPROJ_OUT + DINNER + j];
    }
    float nA[DSTATE], h[DSTATE];
    bool fast = alog_is_arange(A_log, d, nA);
    #pragma unroll
    for (int s = 0; s < DSTATE; s++) h[s] = 0.f;
    __syncthreads();

    size_t o = ((size_t)(b*NCH + c)*DINNER + d)*DSTATE;
    if (fast) {
        float sdt = 0.f;
        for (int t = 0; t < CHUNK; t++) {
            float dt  = dbc[(size_t)(t0+t)*XPROJ_OUT + d];
            float x   = xc [(size_t)(t0+t)*DINNER + d];
            float dtx = dt * x;
            sdt += dt;
            float p = __expf(-dt);
            const float* bc = &sBC[t*32];
            float a = 1.f;
            #pragma unroll
            for (int s = 0; s < DSTATE; s++) {
                a *= p;
                h[s] = a*h[s] + dtx*bc[s];
            }
        }
        float qv = __expf(-sdt);
        float ap = 1.f;
        #pragma unroll
        for (int s = 0; s < DSTATE; s++) {
            ap *= qv;
            carryP[o+s] = ap; carryF[o+s] = h[s];
        }
    } else {
        float ap[DSTATE];
        #pragma unroll
        for (int s = 0; s < DSTATE; s++) ap[s] = 1.f;
        for (int t = 0; t < CHUNK; t++) {
            float dt  = dbc[(size_t)(t0+t)*XPROJ_OUT + d];
            float x   = xc [(size_t)(t0+t)*DINNER + d];
            float dtx = dt * x;
            const float* bc = &sBC[t*32];
            #pragma unroll
            for (int s = 0; s < DSTATE; s++) {
                float a = __expf(dt * nA[s]);
                h[s]  = a*h[s] + dtx*bc[s];
                ap[s] *= a;
            }
        }
        #pragma unroll
        for (int s = 0; s < DSTATE; s++) { carryP[o+s] = ap[s]; carryF[o+s] = h[s]; }
    }
}

// ---------------- K6: scan phase B (sequential carry combine) ---------------
__global__ void scan_phaseB_kernel(const float* __restrict__ carryP,
                                   const float* __restrict__ carryF,
                                   float* __restrict__ hinit)
{
    int idx = blockIdx.x * blockDim.x + threadIdx.x;
    if (idx >= 2*BSZ*DINNER*DSTATE) return;
    int z  = idx / (BSZ*DINNER*DSTATE);
    int r  = idx % (BSZ*DINNER*DSTATE);
    int b  = r / (DINNER*DSTATE);
    int ds = r % (DINNER*DSTATE);
    size_t zoff = (size_t)z*CARRY_PER_Z;
    float h = 0.f;
    for (int c = 0; c < NCH; c++) {
        size_t o = zoff + (size_t)(b*NCH + c)*(DINNER*DSTATE) + ds;
        hinit[o] = h;
        h = carryF[o] + carryP[o]*h;
    }
}

// ---------------- K7: scan phase C (final scan + y + D skip + silu(z) gate) -
__global__ void scan_phaseC_kernel(const float* __restrict__ dbc_,
                                   const float* __restrict__ xc_,
                                   const float* __restrict__ xz_,
                                   const float* __restrict__ Al0, const float* __restrict__ Al1,
                                   const float* __restrict__ Dp0, const float* __restrict__ Dp1,
                                   const float* __restrict__ hinit_,
                                   float* __restrict__ yg_)
{
    __shared__ float sBC[CHUNK*32];
    int z = blockIdx.z;
    const float* A_log = z ? Al1 : Al0;
    const float* Dp    = z ? Dp1 : Dp0;
    const float* dbc = dbc_ + (size_t)z*TOK*XPROJ_OUT;
    const float* xc  = xc_  + (size_t)z*TOK*DINNER;
    const float* xz  = xz_  + (size_t)z*TOK*2*DINNER;
    const float* hinit = hinit_ + (size_t)z*CARRY_PER_Z;
    float* yg = yg_ + (size_t)z*TOK*DINNER;

    int d = threadIdx.x;
    int c = blockIdx.x;
    int b = blockIdx.y;
    int t0 = b*SEQ + c*CHUNK;
    for (int i = d; i < CHUNK*32; i += DINNER) {
        int tt = i >> 5, j = i & 31;
        sBC[i] = dbc[(size_t)(t0+tt)*XPROJ_OUT + DINNER + j];
    }
    float nA[DSTATE], h[DSTATE];
    bool fast = alog_is_arange(A_log, d, nA);
    size_t hb = (size_t)(b*NCH + c)*(DINNER*DSTATE) + d*DSTATE;
    #pragma unroll
    for (int s = 0; s < DSTATE; s++) h[s] = hinit[hb + s];
    float Dd = Dp[d];
    __syncthreads();

    if (fast) {
        for (int t = 0; t < CHUNK; t++) {
            float dt  = dbc[(size_t)(t0+t)*XPROJ_OUT + d];
            float x   = xc [(size_t)(t0+t)*DINNER + d];
            float dtx = dt * x;
            float p = __expf(-dt);
            const float* bc = &sBC[t*32];
            float y = 0.f, a = 1.f;
            #pragma unroll
            for (int s = 0; s < DSTATE; s++) {
                a *= p;
                h[s] = a*h[s] + dtx*bc[s];
                y += h[s] * bc[16 + s];
            }
            float yv = y + x*Dd;
            float zz = xz[(size_t)(t0+t)*(2*DINNER) + DINNER + d];
            yg[(size_t)(t0+t)*DINNER + d] = yv * (zz / (1.f + __expf(-zz)));
        }
    } else {
        for (int t = 0; t < CHUNK; t++) {
            float dt  = dbc[(size_t)(t0+t)*XPROJ_OUT + d];
            float x   = xc [(size_t)(t0+t)*DINNER + d];
            float dtx = dt * x;
            const float* bc = &sBC[t*32];
            float y = 0.f;
            #pragma unroll
            for (int s = 0; s < DSTATE; s++) {
                float a = __expf(dt * nA[s]);
                h[s] = a*h[s] + dtx*bc[s];
                y += h[s] * bc[16 + s];
            }
            float yv = y + x*Dd;
            float zz = xz[(size_t)(t0+t)*(2*DINNER) + DINNER + d];
            yg[(size_t)(t0+t)*DINNER + d] = yv * (zz / (1.f + __expf(-zz)));
        }
    }
}

// ---------------- launch -----------------------------------------------------
extern "C" void kernel_launch(void* const* d_in, const int* in_sizes, int n_in,
                              void* d_out, int out_size)
{
    const float* x1   = (const float*)d_in[0];
    const float* x2   = (const float*)d_in[1];
    const float* ln1g = (const float*)d_in[2];
    const float* ln1b = (const float*)d_in[3];
    const float* ln2g = (const float*)d_in[4];
    const float* ln2b = (const float*)d_in[5];

    const float* in_w[2], *conv_w[2], *conv_b[2], *xproj_w[2], *dt_w[2],
               * dt_b[2], *A_log[2], *Dp[2], *out_w[2];
    for (int mi = 0; mi < 2; mi++) {
        int base = 6 + mi*9;
        in_w[mi]    = (const float*)d_in[base + 0];
        conv_w[mi]  = (const float*)d_in[base + 1];
        conv_b[mi]  = (const float*)d_in[base + 2];
        xproj_w[mi] = (const float*)d_in[base + 3];
        dt_w[mi]    = (const float*)d_in[base + 4];
        dt_b[mi]    = (const float*)d_in[base + 5];
        A_log[mi]   = (const float*)d_in[base + 6];
        Dp[mi]      = (const float*)d_in[base + 7];
        out_w[mi]   = (const float*)d_in[base + 8];
    }

    float *xs, *xz, *xc, *dbc, *w2, *cP, *cF, *hin, *yg;
    cudaGetSymbolAddress((void**)&xs,  g_xs);
    cudaGetSymbolAddress((void**)&xz,  g_xz);
    cudaGetSymbolAddress((void**)&xc,  g_xc);
    cudaGetSymbolAddress((void**)&dbc, g_dbc);
    cudaGetSymbolAddress((void**)&w2,  g_w2);
    cudaGetSymbolAddress((void**)&cP,  g_carryP);
    cudaGetSymbolAddress((void**)&cF,  g_carryF);
    cudaGetSymbolAddress((void**)&hin, g_hinit);
    cudaGetSymbolAddress((void**)&yg,  g_yg);

    float* out0 = (float*)d_out;
    float* out1 = (float*)d_out + (size_t)TOK*DIMC;

    ln_swap_shuffle_kernel<<<TOK/8, 256>>>(x1, x2, ln1g, ln1b, ln2g, ln2b, xs);

    prep_w2_kernel<<<(2*XPROJ_OUT*DINNER + 255)/256, 256>>>(
        xproj_w[0], dt_w[0], xproj_w[1], dt_w[1], w2);

    {   // in_proj: [12800,96] x [384,96]^T
        dim3 grid(TOK/BM, (2*DINNER + BN - 1)/BN, 2);
        gemm_kernel<0, DIMC><<<grid, 256>>>(
            xs, xs + (size_t)TOK*DIMC,
            in_w[0], in_w[1],
            xz, xz + (size_t)TOK*2*DINNER,
            2*DINNER, nullptr, nullptr, nullptr, nullptr);
    }

    {   // depthwise conv + silu
        dim3 grid(SEQ/CTPB/4, BSZ, 2);
        conv_silu_kernel<<<grid, 192>>>(xz, conv_w[0], conv_w[1], conv_b[0], conv_b[1], xc);
    }

    {   // fused xproj+dtproj
        dim3 grid(TOK/BM, (XPROJ_OUT + BN - 1)/BN, 2);
        gemm_kernel<1, DINNER><<<grid, 256>>>(
            xc, xc + (size_t)TOK*DINNER,
            w2, w2 + (size_t)XPROJ_OUT*DINNER,
            dbc, dbc + (size_t)TOK*XPROJ_OUT,
            XPROJ_OUT, dt_b[0], dt_b[1], nullptr, nullptr);
    }

    {   // chunked parallel scan
        dim3 grid(NCH, BSZ, 2);
        scan_phaseA_kernel<<<grid, DINNER>>>(dbc, xc, A_log[0], A_log[1], cP, cF);
        scan_phaseB_kernel<<<(2*BSZ*DINNER*DSTATE + 255)/256, 256>>>(cP, cF, hin);
        scan_phaseC_kernel<<<grid, DINNER>>>(dbc, xc, xz, A_log[0], A_log[1],
                                             Dp[0], Dp[1], hin, yg);
    }

    {   // out_proj + residual
        dim3 grid(TOK/BM, (DIMC + BN - 1)/BN, 2);
        gemm_kernel<2, DINNER><<<grid, 256>>>(
            yg, yg + (size_t)TOK*DINNER,
            out_w[0], out_w[1],
            out0, out1,
            DIMC, nullptr, nullptr, x1, x2);
    }
}

// round 5
// speedup vs baseline: 1.6193x; 1.3666x over previous
#include <cuda_runtime.h>
#include <cuda_bf16.h>
#include <math.h>
#include <stdint.h>

#define DIMC   96
#define DINNER 192
#define DSTATE 16
#define DCONV  4
#define DTRANK 6
#define NSWAP  59
#define BSZ    2
#define SEQ    6400
#define TOK    (BSZ*SEQ)     // 12800
#define CHUNK  32
#define NCH    (SEQ/CHUNK)   // 200
#define XPROJ_OUT 224
#define CARRY_PER_Z (BSZ*NCH*DINNER*DSTATE)

// ---------------- scratch (static device globals; no allocation) ------------
__device__ __align__(16) float g_xs [2*TOK*DIMC];
__device__ __align__(16) float g_xz [2*TOK*2*DINNER];
__device__ __align__(16) float g_xc [2*TOK*DINNER];
__device__ __align__(16) float g_dbc[2*TOK*XPROJ_OUT];
__device__ __align__(16) float g_w2 [2*XPROJ_OUT*DINNER];
__device__ __align__(16) float g_carryP[2*CARRY_PER_Z];
__device__ __align__(16) float g_carryF[2*CARRY_PER_Z];
__device__ __align__(16) float g_hinit [2*CARRY_PER_Z];
__device__ __align__(16) float g_yg [2*TOK*DINNER];

// ================= helpers ===================================================
__device__ __forceinline__ uint32_t smem_u32(const void* p) {
    uint32_t a;
    asm("{ .reg .u64 t; cvta.to.shared.u64 t, %1; cvt.u32.u64 %0, t; }"
        : "=r"(a) : "l"(p));
    return a;
}
__device__ __forceinline__ uint2 pack4bf(float a, float b, float c, float d) {
    __nv_bfloat162 p0 = __floats2bfloat162_rn(a, b);
    __nv_bfloat162 p1 = __floats2bfloat162_rn(c, d);
    uint2 r;
    r.x = *reinterpret_cast<uint32_t*>(&p0);
    r.y = *reinterpret_cast<uint32_t*>(&p1);
    return r;
}
#define LDMX4(r0, r1, r2, r3, addr) \
    asm volatile("ldmatrix.sync.aligned.m8n8.x4.shared.b16 {%0,%1,%2,%3}, [%4];" \
                 : "=r"(r0), "=r"(r1), "=r"(r2), "=r"(r3) : "r"(addr))
#define MMA16816(c, a, b0, b1) \
    asm volatile("mma.sync.aligned.m16n8k16.row.col.f32.bf16.bf16.f32 " \
                 "{%0,%1,%2,%3}, {%4,%5,%6,%7}, {%8,%9}, {%0,%1,%2,%3};" \
                 : "+f"((c)[0]), "+f"((c)[1]), "+f"((c)[2]), "+f"((c)[3]) \
                 : "r"((a)[0]), "r"((a)[1]), "r"((a)[2]), "r"((a)[3]), \
                   "r"(b0), "r"(b1))

// ================= split-bf16 HMMA GEMM =====================================
// O[12800, NTOT] = A[12800, K] @ W[NTOT, K]^T  (+epilogue), split-precision:
// A = Ah + Al, W = Wh + Wl (bf16); acc += Ah*Wh + Ah*Wl + Al*Wh in fp32.
// CTA tile 128x64, 8 warps (4 M x 2 N), warp tile 32x32, K chunked by 96.
// MODE 0: plain  MODE 1: softplus(v+bias[col]) for col<192  MODE 2: +resid
#define SLD 104                        // padded bf16 row stride
#define ABUF (128*SLD*2)               // 26624 B
#define WBUF (64*SLD*2)                // 13312 B
#define SMEM_GEMM (2*ABUF + 2*WBUF)    // 79872 B

template<int MODE, int K, int NTOT>
__global__ void __launch_bounds__(256, 2)
hmma_gemm_kernel(const float* __restrict__ A0, const float* __restrict__ A1,
                 const float* __restrict__ W0, const float* __restrict__ W1,
                 float* __restrict__ O0, float* __restrict__ O1,
                 const float* __restrict__ bi0, const float* __restrict__ bi1,
                 const float* __restrict__ rs0, const float* __restrict__ rs1)
{
    extern __shared__ __align__(16) char sm[];
    char* pAh = sm;
    char* pAl = sm + ABUF;
    char* pWh = sm + 2*ABUF;
    char* pWl = sm + 2*ABUF + WBUF;

    int z = blockIdx.z;
    const float* A     = z ? A1 : A0;
    const float* W     = z ? W1 : W0;
    float*       O     = z ? O1 : O0;
    const float* bias  = z ? bi1 : bi0;
    const float* resid = z ? rs1 : rs0;

    int tid  = threadIdx.x;
    int wid  = tid >> 5;
    int lane = tid & 31;
    int wm   = wid & 3;        // warp M index (32 rows each)
    int wn   = wid >> 2;       // warp N index (32 cols each)
    int m0 = blockIdx.x * 128;
    int n0 = blockIdx.y * 64;

    uint32_t sbase = smem_u32(sm);
    // ldmatrix lane offsets (bytes), excluding k-step and im/jn advance
    uint32_t aoff = (uint32_t)(((wm*32 + (lane & 15))*SLD + ((lane >> 4) << 3)) * 2);
    uint32_t boff = (uint32_t)(((wn*32 + ((lane >> 4) << 3) + (lane & 7))*SLD
                               + (((lane >> 3) & 1) << 3)) * 2);

    float acc[2][4][4] = {};

    #pragma unroll
    for (int kb = 0; kb < K; kb += 96) {
        if (kb) __syncthreads();
        // ---- fill A (128 x 96) hi/lo ----
        #pragma unroll
        for (int p = 0; p < 12; p++) {
            int i  = tid + p*256;
            int r  = i / 24;
            int c4 = (i % 24) * 4;
            float4 av = *reinterpret_cast<const float4*>(
                A + (size_t)(m0 + r)*K + kb + c4);
            __nv_bfloat16 hx = __float2bfloat16(av.x), hy = __float2bfloat16(av.y);
            __nv_bfloat16 hz = __float2bfloat16(av.z), hw = __float2bfloat16(av.w);
            int off = (r*SLD + c4) * 2;
            *reinterpret_cast<uint2*>(pAh + off) =
                pack4bf(__bfloat162float(hx), __bfloat162float(hy),
                        __bfloat162float(hz), __bfloat162float(hw));
            *reinterpret_cast<uint2*>(pAl + off) =
                pack4bf(av.x - __bfloat162float(hx), av.y - __bfloat162float(hy),
                        av.z - __bfloat162float(hz), av.w - __bfloat162float(hw));
        }
        // ---- fill W (64 x 96) hi/lo ----
        #pragma unroll
        for (int p = 0; p < 6; p++) {
            int i  = tid + p*256;
            int r  = i / 24;
            int c4 = (i % 24) * 4;
            int n  = n0 + r;
            float4 wv = make_float4(0.f, 0.f, 0.f, 0.f);
            if (NTOT % 64 == 0 || n < NTOT)
                wv = *reinterpret_cast<const float4*>(W + (size_t)n*K + kb + c4);
            __nv_bfloat16 hx = __float2bfloat16(wv.x), hy = __float2bfloat16(wv.y);
            __nv_bfloat16 hz = __float2bfloat16(wv.z), hw = __float2bfloat16(wv.w);
            int off = (r*SLD + c4) * 2;
            *reinterpret_cast<uint2*>(pWh + off) =
                pack4bf(__bfloat162float(hx), __bfloat162float(hy),
                        __bfloat162float(hz), __bfloat162float(hw));
            *reinterpret_cast<uint2*>(pWl + off) =
                pack4bf(wv.x - __bfloat162float(hx), wv.y - __bfloat162float(hy),
                        wv.z - __bfloat162float(hz), wv.w - __bfloat162float(hw));
        }
        __syncthreads();

        // ---- compute 6 k-steps of 16 ----
        #pragma unroll
        for (int ks = 0; ks < 96; ks += 16) {
            uint32_t ah[2][4], al[2][4], bh[2][4], bl[2][4];
            #pragma unroll
            for (int im = 0; im < 2; im++) {
                uint32_t ad = sbase + aoff + (uint32_t)(im*16*SLD*2 + ks*2);
                LDMX4(ah[im][0], ah[im][1], ah[im][2], ah[im][3], ad);
                LDMX4(al[im][0], al[im][1], al[im][2], al[im][3], ad + ABUF);
            }
            #pragma unroll
            for (int jn = 0; jn < 2; jn++) {
                uint32_t bd = sbase + (uint32_t)(2*ABUF) + boff
                            + (uint32_t)(jn*16*SLD*2 + ks*2);
                LDMX4(bh[jn][0], bh[jn][1], bh[jn][2], bh[jn][3], bd);
                LDMX4(bl[jn][0], bl[jn][1], bl[jn][2], bl[jn][3], bd + WBUF);
            }
            #pragma unroll
            for (int im = 0; im < 2; im++) {
                #pragma unroll
                for (int j = 0; j < 4; j++) {
                    uint32_t b0h = bh[j >> 1][(j & 1)*2], b1h = bh[j >> 1][(j & 1)*2 + 1];
                    uint32_t b0l = bl[j >> 1][(j & 1)*2], b1l = bl[j >> 1][(j & 1)*2 + 1];
                    MMA16816(acc[im][j], ah[im], b0h, b1h);
                    MMA16816(acc[im][j], ah[im], b0l, b1l);
                    MMA16816(acc[im][j], al[im], b0h, b1h);
                }
            }
        }
    }

    // ---- epilogue ----
    #pragma unroll
    for (int im = 0; im < 2; im++) {
        #pragma unroll
        for (int j = 0; j < 4; j++) {
            int col = n0 + wn*32 + j*8 + (lane & 3)*2;
            if (NTOT % 64 != 0 && col >= NTOT) continue;
            int r0 = m0 + wm*32 + im*16 + (lane >> 2);
            #pragma unroll
            for (int half = 0; half < 2; half++) {
                int row = r0 + half*8;
                float v0 = acc[im][j][half*2 + 0];
                float v1 = acc[im][j][half*2 + 1];
                if (MODE == 1) {
                    if (col < DINNER) {
                        float t0 = v0 + bias[col];
                        float t1 = v1 + bias[col + 1];
                        v0 = (t0 > 20.f) ? t0 : log1pf(__expf(t0));
                        v1 = (t1 > 20.f) ? t1 : log1pf(__expf(t1));
                    }
                } else if (MODE == 2) {
                    v0 += resid[(size_t)row*NTOT + col];
                    v1 += resid[(size_t)row*NTOT + col + 1];
                }
                *reinterpret_cast<float2*>(O + (size_t)row*NTOT + col) =
                    make_float2(v0, v1);
            }
        }
    }
}

// ---------------- K0: fold dt_w @ xproj_w[:6] and pack B/C rows (both z) ----
__global__ void prep_w2_kernel(const float* __restrict__ xp0, const float* __restrict__ dw0,
                               const float* __restrict__ xp1, const float* __restrict__ dw1,
                               float* __restrict__ w2)
{
    int idx = blockIdx.x * blockDim.x + threadIdx.x;
    if (idx >= 2*XPROJ_OUT*DINNER) return;
    int z = idx / (XPROJ_OUT*DINNER);
    int e = idx % (XPROJ_OUT*DINNER);
    const float* xproj = z ? xp1 : xp0;
    const float* dtw   = z ? dw1 : dw0;
    int r = e / DINNER, c = e % DINNER;
    float v;
    if (r < DINNER) {
        v = 0.f;
        #pragma unroll
        for (int j = 0; j < DTRANK; j++)
            v += dtw[r*DTRANK + j] * xproj[j*DINNER + c];
    } else if (r < DINNER + DSTATE) {
        v = xproj[(DTRANK + (r - DINNER))*DINNER + c];
    } else {
        v = xproj[(DTRANK + DSTATE + (r - DINNER - DSTATE))*DINNER + c];
    }
    w2[idx] = v;
}

// ---------------- K1: layernorm + token-swap + channel shuffle --------------
__global__ void ln_swap_shuffle_kernel(const float* __restrict__ x1,
                                       const float* __restrict__ x2,
                                       const float* __restrict__ g1, const float* __restrict__ b1,
                                       const float* __restrict__ g2, const float* __restrict__ b2,
                                       float* __restrict__ xs)
{
    __shared__ float s1[8][DIMC];
    __shared__ float s2[8][DIMC];
    int w = threadIdx.x >> 5, lane = threadIdx.x & 31;
    int token = blockIdx.x * 8 + w;
    const float* p1 = x1 + (size_t)token*DIMC;
    const float* p2 = x2 + (size_t)token*DIMC;
    float a0 = p1[lane], a1 = p1[lane+32], a2 = p1[lane+64];
    float c0 = p2[lane], c1 = p2[lane+32], c2 = p2[lane+64];
    float sum1 = a0+a1+a2, sq1 = a0*a0+a1*a1+a2*a2;
    float sum2 = c0+c1+c2, sq2 = c0*c0+c1*c1+c2*c2;
    #pragma unroll
    for (int o = 16; o > 0; o >>= 1) {
        sum1 += __shfl_xor_sync(0xffffffffu, sum1, o);
        sq1  += __shfl_xor_sync(0xffffffffu, sq1,  o);
        sum2 += __shfl_xor_sync(0xffffffffu, sum2, o);
        sq2  += __shfl_xor_sync(0xffffffffu, sq2,  o);
    }
    float m1 = sum1 * (1.f/DIMC), v1 = sq1 * (1.f/DIMC) - m1*m1;
    float m2 = sum2 * (1.f/DIMC), v2 = sq2 * (1.f/DIMC) - m2*m2;
    float r1 = rsqrtf(v1 + 1e-5f), r2 = rsqrtf(v2 + 1e-5f);
    #pragma unroll
    for (int k = 0; k < 3; k++) {
        int ch = lane + 32*k;
        float xv = (k==0? a0 : k==1? a1 : a2);
        float yv = (k==0? c0 : k==1? c1 : c2);
        s1[w][ch] = (xv - m1) * r1 * g1[ch] + b1[ch];
        s2[w][ch] = (yv - m2) * r2 * g2[ch] + b2[ch];
    }
    __syncwarp();
    #pragma unroll
    for (int k = 0; k < 3; k++) {
        int ch  = lane + 32*k;
        int src = (ch & 1)*48 + (ch >> 1);        // channel shuffle (groups=2)
        float p2v = s2[w][src];                   // x2s == shuffled x2n
        float p1v = (src < NSWAP) ? s2[w][src] : s1[w][src];
        xs[(size_t)token*DIMC + ch]         = p1v;
        xs[(size_t)(TOK + token)*DIMC + ch] = p2v;
    }
}

// ---------------- K3: depthwise causal conv(4)+silu, sliding window ---------
#define CTPB 8
__global__ void conv_silu_kernel(const float* __restrict__ xz,
                                 const float* __restrict__ cw0, const float* __restrict__ cw1,
                                 const float* __restrict__ cb0, const float* __restrict__ cb1,
                                 float* __restrict__ xc)
{
    int z = blockIdx.z;
    const float* cw = z ? cw1 : cw0;
    const float* cb = z ? cb1 : cb0;
    const float* xzp = xz + (size_t)z*TOK*2*DINNER;
    float*       xcp = xc + (size_t)z*TOK*DINNER;

    int tid = threadIdx.x;
    int q   = tid % 48;
    int tb  = blockIdx.x * 4 + tid / 48;
    int b   = blockIdx.y;
    int t0  = tb * CTPB;
    int d   = q * 4;

    float w00=cw[(d+0)*4+0], w01=cw[(d+0)*4+1], w02=cw[(d+0)*4+2], w03=cw[(d+0)*4+3];
    float w10=cw[(d+1)*4+0], w11=cw[(d+1)*4+1], w12=cw[(d+1)*4+2], w13=cw[(d+1)*4+3];
    float w20=cw[(d+2)*4+0], w21=cw[(d+2)*4+1], w22=cw[(d+2)*4+2], w23=cw[(d+2)*4+3];
    float w30=cw[(d+3)*4+0], w31=cw[(d+3)*4+1], w32=cw[(d+3)*4+2], w33=cw[(d+3)*4+3];
    float4 bias = *reinterpret_cast<const float4*>(cb + d);

    const float* xrow = xzp + (size_t)(b*SEQ)*(2*DINNER) + d;
    float4 h0, h1, h2;
    {
        int tt = t0 - 3;
        h0 = (tt >= 0) ? *reinterpret_cast<const float4*>(xrow + (size_t)tt*(2*DINNER))
                       : make_float4(0.f,0.f,0.f,0.f);
        tt = t0 - 2;
        h1 = (tt >= 0) ? *reinterpret_cast<const float4*>(xrow + (size_t)tt*(2*DINNER))
                       : make_float4(0.f,0.f,0.f,0.f);
        tt = t0 - 1;
        h2 = (tt >= 0) ? *reinterpret_cast<const float4*>(xrow + (size_t)tt*(2*DINNER))
                       : make_float4(0.f,0.f,0.f,0.f);
    }
    #pragma unroll
    for (int t = t0; t < t0 + CTPB; t++) {
        float4 h3 = *reinterpret_cast<const float4*>(xrow + (size_t)t*(2*DINNER));
        float4 o;
        o.x = bias.x + w00*h0.x + w01*h1.x + w02*h2.x + w03*h3.x;
        o.y = bias.y + w10*h0.y + w11*h1.y + w12*h2.y + w13*h3.y;
        o.z = bias.z + w20*h0.z + w21*h1.z + w22*h2.z + w23*h3.z;
        o.w = bias.w + w30*h0.w + w31*h1.w + w32*h2.w + w33*h3.w;
        o.x = o.x / (1.f + __expf(-o.x));
        o.y = o.y / (1.f + __expf(-o.y));
        o.z = o.z / (1.f + __expf(-o.z));
        o.w = o.w / (1.f + __expf(-o.w));
        *reinterpret_cast<float4*>(xcp + (size_t)(b*SEQ + t)*DINNER + d) = o;
        h0 = h1; h1 = h2; h2 = h3;
    }
}

// helper: does this A_log row equal log(1..16)? (fast-path eligibility)
__device__ __forceinline__ bool alog_is_arange(const float* A_log, int d, float nA[DSTATE])
{
    bool fast = true;
    #pragma unroll
    for (int s = 0; s < DSTATE; s++) {
        nA[s] = -__expf(A_log[d*DSTATE + s]);
        fast = fast && (fabsf(nA[s] + (float)(s+1)) <= 1e-4f * (float)(s+1));
    }
    return fast;
}

// ---------------- K5: scan phase A (per-chunk carry, zero init) -------------
__global__ void scan_phaseA_kernel(const float* __restrict__ dbc_,
                                   const float* __restrict__ xc_,
                                   const float* __restrict__ Al0, const float* __restrict__ Al1,
                                   float* __restrict__ carryP_,
                                   float* __restrict__ carryF_)
{
    __shared__ float sBC[CHUNK*32];
    int z = blockIdx.z;
    const float* A_log = z ? Al1 : Al0;
    const float* dbc = dbc_ + (size_t)z*TOK*XPROJ_OUT;
    const float* xc  = xc_  + (size_t)z*TOK*DINNER;
    float* carryP = carryP_ + (size_t)z*CARRY_PER_Z;
    float* carryF = carryF_ + (size_t)z*CARRY_PER_Z;

    int d = threadIdx.x;
    int c = blockIdx.x;
    int b = blockIdx.y;
    int t0 = b*SEQ + c*CHUNK;
    for (int i = d; i < CHUNK*32; i += DINNER) {
        int tt = i >> 5, j = i & 31;
        sBC[i] = dbc[(size_t)(t0+tt)*XPROJ_OUT + DINNER + j];
    }
    float nA[DSTATE], h[DSTATE];
    bool fast = alog_is_arange(A_log, d, nA);
    #pragma unroll
    for (int s = 0; s < DSTATE; s++) h[s] = 0.f;
    __syncthreads();

    size_t o = ((size_t)(b*NCH + c)*DINNER + d)*DSTATE;
    if (fast) {
        float sdt = 0.f;
        for (int t = 0; t < CHUNK; t++) {
            float dt  = dbc[(size_t)(t0+t)*XPROJ_OUT + d];
            float x   = xc [(size_t)(t0+t)*DINNER + d];
            float dtx = dt * x;
            sdt += dt;
            float p = __expf(-dt);
            const float* bc = &sBC[t*32];
            float a = 1.f;
            #pragma unroll
            for (int s = 0; s < DSTATE; s++) {
                a *= p;
                h[s] = a*h[s] + dtx*bc[s];
            }
        }
        float qv = __expf(-sdt);
        float ap = 1.f;
        #pragma unroll
        for (int s = 0; s < DSTATE; s++) {
            ap *= qv;
            carryP[o+s] = ap; carryF[o+s] = h[s];
        }
    } else {
        float ap[DSTATE];
        #pragma unroll
        for (int s = 0; s < DSTATE; s++) ap[s] = 1.f;
        for (int t = 0; t < CHUNK; t++) {
            float dt  = dbc[(size_t)(t0+t)*XPROJ_OUT + d];
            float x   = xc [(size_t)(t0+t)*DINNER + d];
            float dtx = dt * x;
            const float* bc = &sBC[t*32];
            #pragma unroll
            for (int s = 0; s < DSTATE; s++) {
                float a = __expf(dt * nA[s]);
                h[s]  = a*h[s] + dtx*bc[s];
                ap[s] *= a;
            }
        }
        #pragma unroll
        for (int s = 0; s < DSTATE; s++) { carryP[o+s] = ap[s]; carryF[o+s] = h[s]; }
    }
}

// ---------------- K6: scan phase B (sequential carry combine) ---------------
__global__ void scan_phaseB_kernel(const float* __restrict__ carryP,
                                   const float* __restrict__ carryF,
                                   float* __restrict__ hinit)
{
    int idx = blockIdx.x * blockDim.x + threadIdx.x;
    if (idx >= 2*BSZ*DINNER*DSTATE) return;
    int z  = idx / (BSZ*DINNER*DSTATE);
    int r  = idx % (BSZ*DINNER*DSTATE);
    int b  = r / (DINNER*DSTATE);
    int ds = r % (DINNER*DSTATE);
    size_t zoff = (size_t)z*CARRY_PER_Z;
    float h = 0.f;
    #pragma unroll 4
    for (int c = 0; c < NCH; c++) {
        size_t o = zoff + (size_t)(b*NCH + c)*(DINNER*DSTATE) + ds;
        hinit[o] = h;
        h = carryF[o] + carryP[o]*h;
    }
}

// ---------------- K7: scan phase C (final scan + y + D skip + silu(z) gate) -
__global__ void scan_phaseC_kernel(const float* __restrict__ dbc_,
                                   const float* __restrict__ xc_,
                                   const float* __restrict__ xz_,
                                   const float* __restrict__ Al0, const float* __restrict__ Al1,
                                   const float* __restrict__ Dp0, const float* __restrict__ Dp1,
                                   const float* __restrict__ hinit_,
                                   float* __restrict__ yg_)
{
    __shared__ float sBC[CHUNK*32];
    int z = blockIdx.z;
    const float* A_log = z ? Al1 : Al0;
    const float* Dp    = z ? Dp1 : Dp0;
    const float* dbc = dbc_ + (size_t)z*TOK*XPROJ_OUT;
    const float* xc  = xc_  + (size_t)z*TOK*DINNER;
    const float* xz  = xz_  + (size_t)z*TOK*2*DINNER;
    const float* hinit = hinit_ + (size_t)z*CARRY_PER_Z;
    float* yg = yg_ + (size_t)z*TOK*DINNER;

    int d = threadIdx.x;
    int c = blockIdx.x;
    int b = blockIdx.y;
    int t0 = b*SEQ + c*CHUNK;
    for (int i = d; i < CHUNK*32; i += DINNER) {
        int tt = i >> 5, j = i & 31;
        sBC[i] = dbc[(size_t)(t0+tt)*XPROJ_OUT + DINNER + j];
    }
    float nA[DSTATE], h[DSTATE];
    bool fast = alog_is_arange(A_log, d, nA);
    size_t hb = (size_t)(b*NCH + c)*(DINNER*DSTATE) + d*DSTATE;
    #pragma unroll
    for (int s = 0; s < DSTATE; s++) h[s] = hinit[hb + s];
    float Dd = Dp[d];
    __syncthreads();

    if (fast) {
        for (int t = 0; t < CHUNK; t++) {
            float dt  = dbc[(size_t)(t0+t)*XPROJ_OUT + d];
            float x   = xc [(size_t)(t0+t)*DINNER + d];
            float dtx = dt * x;
            float p = __expf(-dt);
            const float* bc = &sBC[t*32];
            float y = 0.f, a = 1.f;
            #pragma unroll
            for (int s = 0; s < DSTATE; s++) {
                a *= p;
                h[s] = a*h[s] + dtx*bc[s];
                y += h[s] * bc[16 + s];
            }
            float yv = y + x*Dd;
            float zz = xz[(size_t)(t0+t)*(2*DINNER) + DINNER + d];
            yg[(size_t)(t0+t)*DINNER + d] = yv * (zz / (1.f + __expf(-zz)));
        }
    } else {
        for (int t = 0; t < CHUNK; t++) {
            float dt  = dbc[(size_t)(t0+t)*XPROJ_OUT + d];
            float x   = xc [(size_t)(t0+t)*DINNER + d];
            float dtx = dt * x;
            const float* bc = &sBC[t*32];
            float y = 0.f;
            #pragma unroll
            for (int s = 0; s < DSTATE; s++) {
                float a = __expf(dt * nA[s]);
                h[s] = a*h[s] + dtx*bc[s];
                y += h[s] * bc[16 + s];
            }
            float yv = y + x*Dd;
            float zz = xz[(size_t)(t0+t)*(2*DINNER) + DINNER + d];
            yg[(size_t)(t0+t)*DINNER + d] = yv * (zz / (1.f + __expf(-zz)));
        }
    }
}

// ---------------- launch -----------------------------------------------------
extern "C" void kernel_launch(void* const* d_in, const int* in_sizes, int n_in,
                              void* d_out, int out_size)
{
    const float* x1   = (const float*)d_in[0];
    const float* x2   = (const float*)d_in[1];
    const float* ln1g = (const float*)d_in[2];
    const float* ln1b = (const float*)d_in[3];
    const float* ln2g = (const float*)d_in[4];
    const float* ln2b = (const float*)d_in[5];

    const float* in_w[2], *conv_w[2], *conv_b[2], *xproj_w[2], *dt_w[2],
               * dt_b[2], *A_log[2], *Dp[2], *out_w[2];
    for (int mi = 0; mi < 2; mi++) {
        int base = 6 + mi*9;
        in_w[mi]    = (const float*)d_in[base + 0];
        conv_w[mi]  = (const float*)d_in[base + 1];
        conv_b[mi]  = (const float*)d_in[base + 2];
        xproj_w[mi] = (const float*)d_in[base + 3];
        dt_w[mi]    = (const float*)d_in[base + 4];
        dt_b[mi]    = (const float*)d_in[base + 5];
        A_log[mi]   = (const float*)d_in[base + 6];
        Dp[mi]      = (const float*)d_in[base + 7];
        out_w[mi]   = (const float*)d_in[base + 8];
    }

    float *xs, *xz, *xc, *dbc, *w2, *cP, *cF, *hin, *yg;
    cudaGetSymbolAddress((void**)&xs,  g_xs);
    cudaGetSymbolAddress((void**)&xz,  g_xz);
    cudaGetSymbolAddress((void**)&xc,  g_xc);
    cudaGetSymbolAddress((void**)&dbc, g_dbc);
    cudaGetSymbolAddress((void**)&w2,  g_w2);
    cudaGetSymbolAddress((void**)&cP,  g_carryP);
    cudaGetSymbolAddress((void**)&cF,  g_carryF);
    cudaGetSymbolAddress((void**)&hin, g_hinit);
    cudaGetSymbolAddress((void**)&yg,  g_yg);

    float* out0 = (float*)d_out;
    float* out1 = (float*)d_out + (size_t)TOK*DIMC;

    cudaFuncSetAttribute(hmma_gemm_kernel<0, 96, 384>,
                         cudaFuncAttributeMaxDynamicSharedMemorySize, SMEM_GEMM);
    cudaFuncSetAttribute(hmma_gemm_kernel<1, 192, 224>,
                         cudaFuncAttributeMaxDynamicSharedMemorySize, SMEM_GEMM);
    cudaFuncSetAttribute(hmma_gemm_kernel<2, 192, 96>,
                         cudaFuncAttributeMaxDynamicSharedMemorySize, SMEM_GEMM);

    ln_swap_shuffle_kernel<<<TOK/8, 256>>>(x1, x2, ln1g, ln1b, ln2g, ln2b, xs);

    prep_w2_kernel<<<(2*XPROJ_OUT*DINNER + 255)/256, 256>>>(
        xproj_w[0], dt_w[0], xproj_w[1], dt_w[1], w2);

    {   // in_proj: [12800,96] x [384,96]^T -> xz
        dim3 grid(TOK/128, 384/64, 2);
        hmma_gemm_kernel<0, 96, 384><<<grid, 256, SMEM_GEMM>>>(
            xs, xs + (size_t)TOK*DIMC,
            in_w[0], in_w[1],
            xz, xz + (size_t)TOK*2*DINNER,
            nullptr, nullptr, nullptr, nullptr);
    }

    {   // depthwise conv + silu
        dim3 grid(SEQ/CTPB/4, BSZ, 2);
        conv_silu_kernel<<<grid, 192>>>(xz, conv_w[0], conv_w[1], conv_b[0], conv_b[1], xc);
    }

    {   // fused xproj+dtproj -> dbc (softplus on first 192 cols)
        dim3 grid(TOK/128, (XPROJ_OUT + 63)/64, 2);
        hmma_gemm_kernel<1, 192, 224><<<grid, 256, SMEM_GEMM>>>(
            xc, xc + (size_t)TOK*DINNER,
            w2, w2 + (size_t)XPROJ_OUT*DINNER,
            dbc, dbc + (size_t)TOK*XPROJ_OUT,
            dt_b[0], dt_b[1], nullptr, nullptr);
    }

    {   // chunked parallel scan
        dim3 grid(NCH, BSZ, 2);
        scan_phaseA_kernel<<<grid, DINNER>>>(dbc, xc, A_log[0], A_log[1], cP, cF);
        scan_phaseB_kernel<<<(2*BSZ*DINNER*DSTATE + 255)/256, 256>>>(cP, cF, hin);
        scan_phaseC_kernel<<<grid, DINNER>>>(dbc, xc, xz, A_log[0], A_log[1],
                                             Dp[0], Dp[1], hin, yg);
    }

    {   // out_proj + residual -> d_out
        dim3 grid(TOK/128, (DIMC + 63)/64, 2);
        hmma_gemm_kernel<2, 192, 96><<<grid, 256, SMEM_GEMM>>>(
            yg, yg + (size_t)TOK*DINNER,
            out_w[0], out_w[1],
            out0, out1,
            nullptr, nullptr, x1, x2);
    }
}